// round 4
// baseline (speedup 1.0000x reference)
#include <cuda_runtime.h>
#include <cstddef>

#define ED 1024
#define BD 2048
#define BA 128
#define NITER 500
#define LAMB_C 0.3f
#define H_C 0.005f
#define RMC 0.99f
#define LOWACT 0.001f
#define GRID 128
#define BKC 32

#define O_A     ((size_t)0)
#define O_BASIS ((size_t)(BD*BA))
#define O_HES   (O_BASIS + (size_t)ED*BD)
#define O_L1    (O_HES + BD)
#define O_SNR   (O_L1 + BD)

__device__ float g_BT[(size_t)BD*ED];
__device__ float g_It[(size_t)ED*BA];
__device__ float g_a [(size_t)BD*BA];
__device__ float g_r [(size_t)ED*BA];
__device__ float g_S [(size_t)ED*ED];
__device__ float g_T0[(size_t)ED*ED];   // SQ during power phase, then split-K partials
__device__ float g_T1[(size_t)ED*ED];
__device__ float g_NB[(size_t)ED*BD];
__device__ float g_hes[BD];
__device__ float g_nsq[BD];
__device__ float g_v[ED];
__device__ float g_w[ED];
__device__ float g_scal[8];             // 0:lam 1:eta 2:thr 3:scale 4:sumI2
__device__ unsigned g_cnt;
__device__ volatile unsigned g_gen;

__device__ __forceinline__ float sshrinkf(float v, float thr) {
    float t = fabsf(v) - thr;
    return t > 0.0f ? copysignf(t, v) : 0.0f;
}

// ---- software grid barrier (cooperative-groups pattern) ----
__device__ __forceinline__ void gsync(unsigned gen) {
    __syncthreads();
    if (threadIdx.x == 0) {
        __threadfence();
        unsigned t = atomicAdd(&g_cnt, 1u);
        if (t == GRID - 1) {
            g_cnt = 0;
            __threadfence();
            g_gen = gen;
        } else {
            while (g_gen < gen) { }
            __threadfence();
        }
    }
    __syncthreads();
}

// ---- 16x128 tile GEMM, K=1024, BK=32 double-buffered, 128 thr, 4x4 micro ----
__device__ __forceinline__ void tile_mm(
    const float* __restrict__ A0, size_t lda, const float* __restrict__ Bsrc,
    float (&As)[2][BKC][20], float (&Bs)[2][BKC][128], float (&acc)[4][4], int tid)
{
    const int m = tid >> 3, k4 = (tid & 7) * 4;
    const int warp = tid >> 5, tx = tid & 31;
    float4 ra, rb[8];

    ra = *(const float4*)(A0 + (size_t)m*lda + k4);
    #pragma unroll
    for (int i = 0; i < 8; i++) {
        int s = tid + i*128;
        rb[i] = *(const float4*)(Bsrc + (size_t)(s>>5)*128 + ((s&31)<<2));
    }
    As[0][k4+0][m]=ra.x; As[0][k4+1][m]=ra.y; As[0][k4+2][m]=ra.z; As[0][k4+3][m]=ra.w;
    #pragma unroll
    for (int i = 0; i < 8; i++) {
        int s = tid + i*128;
        *(float4*)&Bs[0][s>>5][(s&31)<<2] = rb[i];
    }

    #pragma unroll 1
    for (int t = 0; t < 32; t++) {
        __syncthreads();
        if (t < 31) {
            int k0 = (t+1)*BKC;
            ra = *(const float4*)(A0 + (size_t)m*lda + k0 + k4);
            #pragma unroll
            for (int i = 0; i < 8; i++) {
                int s = tid + i*128;
                rb[i] = *(const float4*)(Bsrc + (size_t)(k0+(s>>5))*128 + ((s&31)<<2));
            }
        }
        const int b = t & 1;
        #pragma unroll
        for (int kk = 0; kk < BKC; kk++) {
            float4 av = *(const float4*)&As[b][kk][warp*4];
            float4 bv = *(const float4*)&Bs[b][kk][tx*4];
            acc[0][0]=fmaf(av.x,bv.x,acc[0][0]); acc[0][1]=fmaf(av.x,bv.y,acc[0][1]);
            acc[0][2]=fmaf(av.x,bv.z,acc[0][2]); acc[0][3]=fmaf(av.x,bv.w,acc[0][3]);
            acc[1][0]=fmaf(av.y,bv.x,acc[1][0]); acc[1][1]=fmaf(av.y,bv.y,acc[1][1]);
            acc[1][2]=fmaf(av.y,bv.z,acc[1][2]); acc[1][3]=fmaf(av.y,bv.w,acc[1][3]);
            acc[2][0]=fmaf(av.z,bv.x,acc[2][0]); acc[2][1]=fmaf(av.z,bv.y,acc[2][1]);
            acc[2][2]=fmaf(av.z,bv.z,acc[2][2]); acc[2][3]=fmaf(av.z,bv.w,acc[2][3]);
            acc[3][0]=fmaf(av.w,bv.x,acc[3][0]); acc[3][1]=fmaf(av.w,bv.y,acc[3][1]);
            acc[3][2]=fmaf(av.w,bv.z,acc[3][2]); acc[3][3]=fmaf(av.w,bv.w,acc[3][3]);
        }
        if (t < 31) {
            const int nb = (t+1) & 1;
            As[nb][k4+0][m]=ra.x; As[nb][k4+1][m]=ra.y; As[nb][k4+2][m]=ra.z; As[nb][k4+3][m]=ra.w;
            #pragma unroll
            for (int i = 0; i < 8; i++) {
                int s = tid + i*128;
                *(float4*)&Bs[nb][s>>5][(s&31)<<2] = rb[i];
            }
        }
    }
}

// ---- persistent kernel: power iteration + 500 ISTA iterations ----
__global__ void __launch_bounds__(128, 1) persist_k(const float* __restrict__ basis)
{
    __shared__ float As[2][BKC][20];
    __shared__ float Bs[2][BKC][128];
    __shared__ float red1[4], red2[4];
    __shared__ float sh_b;
    const int cta = blockIdx.x, tid = threadIdx.x;
    unsigned gen = 0;

    // ---- power iteration: 8 matvecs on SQ=S^64 (g_T0), then S + Rayleigh ----
    for (int pi = 0; pi < 9; pi++) {
        const float* M = (pi < 8) ? g_T0 : g_S;
        {
            int row = cta*8 + (tid >> 4), l = tid & 15;
            const float* mr = M + (size_t)row*ED;
            float s = 0.0f;
            for (int j = l; j < ED; j += 16) s = fmaf(mr[j], g_v[j], s);
            #pragma unroll
            for (int o = 8; o; o >>= 1) s += __shfl_xor_sync(~0u, s, o, 16);
            if (l == 0) g_w[row] = s;
        }
        gen++; gsync(gen);
        if (cta == 0) {
            if (pi < 8) {
                float x[8], ss = 0.0f;
                #pragma unroll
                for (int i = 0; i < 8; i++) { x[i] = g_w[tid*8+i]; ss += x[i]*x[i]; }
                #pragma unroll
                for (int o = 16; o; o >>= 1) ss += __shfl_xor_sync(~0u, ss, o);
                if ((tid & 31) == 0) red1[tid>>5] = ss;
                __syncthreads();
                if (tid == 0) sh_b = rsqrtf(red1[0]+red1[1]+red1[2]+red1[3]);
                __syncthreads();
                float rs = sh_b;
                #pragma unroll
                for (int i = 0; i < 8; i++) g_v[tid*8+i] = x[i]*rs;
            } else {
                float d1 = 0.0f, d2 = 0.0f;
                #pragma unroll
                for (int i = 0; i < 8; i++) {
                    float vv = g_v[tid*8+i], ww = g_w[tid*8+i];
                    d1 = fmaf(vv, ww, d1); d2 = fmaf(vv, vv, d2);
                }
                #pragma unroll
                for (int o = 16; o; o >>= 1) {
                    d1 += __shfl_xor_sync(~0u, d1, o);
                    d2 += __shfl_xor_sync(~0u, d2, o);
                }
                if ((tid & 31) == 0) { red1[tid>>5] = d1; red2[tid>>5] = d2; }
                __syncthreads();
                if (tid == 0) {
                    float lam = (red1[0]+red1[1]+red1[2]+red1[3]) /
                                (red2[0]+red2[1]+red2[2]+red2[3]);
                    g_scal[0] = lam;
                    g_scal[1] = 1.0f / lam;
                    g_scal[2] = LAMB_C / lam;
                }
                __syncthreads();
            }
        }
        gen++; gsync(gen);
    }

    const float eta = g_scal[1], thr = g_scal[2];
    const int warp = tid >> 5, tx = tid & 31;
    float* p0 = g_T0;
    float* p1 = g_T0 + (size_t)ED*BA;

    // ---- 500 ISTA iterations ----
    for (int it = 0; it < NITER; it++) {
        // Phase A: a = shrink(a + eta * BT(16 rows) * r, thr)
        {
            float acc[4][4] = {};
            tile_mm(g_BT + (size_t)(cta*16)*ED, ED, g_r, As, Bs, acc, tid);
            #pragma unroll
            for (int i = 0; i < 4; i++) {
                int row = cta*16 + warp*4 + i;
                float4* ap = (float4*)&g_a[(size_t)row*BA + tx*4];
                float4 o = *ap;
                o.x = sshrinkf(o.x + eta*acc[i][0], thr);
                o.y = sshrinkf(o.y + eta*acc[i][1], thr);
                o.z = sshrinkf(o.z + eta*acc[i][2], thr);
                o.w = sshrinkf(o.w + eta*acc[i][3], thr);
                *ap = o;
            }
        }
        gen++; gsync(gen);
        // Phase B: split-K2 partials of basis * a
        {
            int row0 = (cta >> 1)*16, koff = (cta & 1)*1024;
            float* pd = (cta & 1) ? p1 : p0;
            float acc[4][4] = {};
            tile_mm(basis + (size_t)row0*BD + koff, BD, g_a + (size_t)koff*BA, As, Bs, acc, tid);
            #pragma unroll
            for (int i = 0; i < 4; i++) {
                int row = row0 + warp*4 + i;
                *(float4*)&pd[(size_t)row*BA + tx*4] =
                    make_float4(acc[i][0], acc[i][1], acc[i][2], acc[i][3]);
            }
        }
        gen++; gsync(gen);
        // Phase C: r = It - p0 - p1
        {
            size_t i0 = (size_t)cta*1024 + (size_t)tid*8;
            #pragma unroll
            for (int h = 0; h < 8; h += 4) {
                float4 iv = *(const float4*)&g_It[i0+h];
                float4 a0 = *(const float4*)&p0[i0+h];
                float4 a1 = *(const float4*)&p1[i0+h];
                *(float4*)&g_r[i0+h] =
                    make_float4(iv.x-a0.x-a1.x, iv.y-a0.y-a1.y, iv.z-a0.z-a1.z, iv.w-a0.w-a1.w);
            }
        }
        gen++; gsync(gen);
    }
}

// ---------------- NT GEMM (graph nodes): C[M,N] = A[M,K] * B[N,K]^T ----------------
// EPI 0: store   EPI 3: store*scale^2   EPI 4: NB = Aux + (H/BA)*acc/(hes+eps)
template<int EPI>
__global__ void __launch_bounds__(128, 2) gemm_nt_k(
    const float* __restrict__ A, const float* __restrict__ Bm,
    float* __restrict__ C, const float* __restrict__ Aux,
    int Nh, int Kh)
{
    __shared__ float As[2][64][18];
    __shared__ float Bs[2][64][68];
    const int tid = threadIdx.x;
    const int tx = tid & 15, ty = tid >> 4;
    const float* Ab = A + (size_t)blockIdx.y * 16 * Kh;
    const float* Bb = Bm + (size_t)blockIdx.x * 64 * Kh;
    const int ar0 = tid >> 4, ar1 = (tid + 128) >> 4, ak = (tid & 15) * 4;

    float4 ra0, ra1, rb[8];
    float acc[2][4] = {{0,0,0,0},{0,0,0,0}};

    ra0 = *(const float4*)(Ab + (size_t)ar0*Kh + ak);
    ra1 = *(const float4*)(Ab + (size_t)ar1*Kh + ak);
    #pragma unroll
    for (int i = 0; i < 8; i++) {
        int q = tid + i*128;
        rb[i] = *(const float4*)(Bb + (size_t)(q>>4)*Kh + (q&15)*4);
    }
    As[0][ak+0][ar0]=ra0.x; As[0][ak+1][ar0]=ra0.y; As[0][ak+2][ar0]=ra0.z; As[0][ak+3][ar0]=ra0.w;
    As[0][ak+0][ar1]=ra1.x; As[0][ak+1][ar1]=ra1.y; As[0][ak+2][ar1]=ra1.z; As[0][ak+3][ar1]=ra1.w;
    #pragma unroll
    for (int i = 0; i < 8; i++) {
        int q = tid + i*128; int n = q>>4; int kq = (q&15)*4;
        Bs[0][kq+0][n]=rb[i].x; Bs[0][kq+1][n]=rb[i].y; Bs[0][kq+2][n]=rb[i].z; Bs[0][kq+3][n]=rb[i].w;
    }

    const int T = Kh >> 6;
    for (int t = 0; t < T; t++) {
        __syncthreads();
        if (t + 1 < T) {
            int k0 = (t+1) * 64;
            ra0 = *(const float4*)(Ab + (size_t)ar0*Kh + k0 + ak);
            ra1 = *(const float4*)(Ab + (size_t)ar1*Kh + k0 + ak);
            #pragma unroll
            for (int i = 0; i < 8; i++) {
                int q = tid + i*128;
                rb[i] = *(const float4*)(Bb + (size_t)(q>>4)*Kh + k0 + (q&15)*4);
            }
        }
        const int buf = t & 1;
        #pragma unroll
        for (int kk = 0; kk < 64; kk++) {
            float2 av = *(const float2*)&As[buf][kk][ty*2];
            float4 bv = *(const float4*)&Bs[buf][kk][tx*4];
            acc[0][0]=fmaf(av.x,bv.x,acc[0][0]); acc[0][1]=fmaf(av.x,bv.y,acc[0][1]);
            acc[0][2]=fmaf(av.x,bv.z,acc[0][2]); acc[0][3]=fmaf(av.x,bv.w,acc[0][3]);
            acc[1][0]=fmaf(av.y,bv.x,acc[1][0]); acc[1][1]=fmaf(av.y,bv.y,acc[1][1]);
            acc[1][2]=fmaf(av.y,bv.z,acc[1][2]); acc[1][3]=fmaf(av.y,bv.w,acc[1][3]);
        }
        if (t + 1 < T) {
            const int nb = (t+1) & 1;
            As[nb][ak+0][ar0]=ra0.x; As[nb][ak+1][ar0]=ra0.y; As[nb][ak+2][ar0]=ra0.z; As[nb][ak+3][ar0]=ra0.w;
            As[nb][ak+0][ar1]=ra1.x; As[nb][ak+1][ar1]=ra1.y; As[nb][ak+2][ar1]=ra1.z; As[nb][ak+3][ar1]=ra1.w;
            #pragma unroll
            for (int i = 0; i < 8; i++) {
                int q = tid + i*128; int n = q>>4; int kq = (q&15)*4;
                Bs[nb][kq+0][n]=rb[i].x; Bs[nb][kq+1][n]=rb[i].y; Bs[nb][kq+2][n]=rb[i].z; Bs[nb][kq+3][n]=rb[i].w;
            }
        }
    }

    const int gm = blockIdx.y*16 + ty*2;
    const int gn = blockIdx.x*64 + tx*4;
    if (EPI == 0) {
        #pragma unroll
        for (int mi = 0; mi < 2; mi++)
            *(float4*)(C + (size_t)(gm+mi)*Nh + gn) =
                make_float4(acc[mi][0],acc[mi][1],acc[mi][2],acc[mi][3]);
    } else if (EPI == 3) {
        const float s2 = g_scal[3] * g_scal[3];
        #pragma unroll
        for (int mi = 0; mi < 2; mi++)
            *(float4*)(C + (size_t)(gm+mi)*Nh + gn) =
                make_float4(acc[mi][0]*s2,acc[mi][1]*s2,acc[mi][2]*s2,acc[mi][3]*s2);
    } else {
        #pragma unroll
        for (int mi = 0; mi < 2; mi++)
            #pragma unroll
            for (int ni = 0; ni < 4; ni++) {
                int col = gn + ni;
                C[(size_t)(gm+mi)*Nh + col] = Aux[(size_t)(gm+mi)*Nh + col] +
                    (H_C/(float)BA) * acc[mi][ni] / (g_hes[col] + LOWACT);
            }
    }
}

// ---------------- helpers ----------------
__global__ void transpose_k(const float* __restrict__ in, float* __restrict__ out,
                            float* __restrict__ out2, int rows, int cols)
{
    __shared__ float sm[32][33];
    int bx = blockIdx.x*32, by = blockIdx.y*32;
    int tx = threadIdx.x, ty = threadIdx.y;
    #pragma unroll
    for (int j = 0; j < 32; j += 8)
        sm[ty+j][tx] = in[(size_t)(by+ty+j)*cols + bx+tx];
    __syncthreads();
    #pragma unroll
    for (int j = 0; j < 32; j += 8) {
        float v = sm[tx][ty+j];
        size_t o = (size_t)(bx+ty+j)*rows + by+tx;
        out[o] = v;
        if (out2) out2[o] = v;
    }
}

__global__ void init_k(float* a) {
    int idx = blockIdx.x*blockDim.x + threadIdx.x;
    if (idx < BD*BA) a[idx] = 0.0f;
    if (idx < ED) g_v[idx] = 1.0f;
    if (idx == 0) { g_scal[4] = 0.0f; g_cnt = 0; g_gen = 0; }
}

__global__ void copyN_k(const float* __restrict__ in, float* __restrict__ out, int n) {
    int i = blockIdx.x*256 + threadIdx.x;
    if (i < n) out[i] = in[i];
}

__global__ void diagmax_k(const float* __restrict__ T) {
    __shared__ float red[32];
    int tid = threadIdx.x;
    float m = fabsf(T[(size_t)tid*ED + tid]);
    #pragma unroll
    for (int o = 16; o; o >>= 1) m = fmaxf(m, __shfl_xor_sync(~0u, m, o));
    if ((tid&31)==0) red[tid>>5] = m;
    __syncthreads();
    if (tid < 32) {
        float mm = red[tid];
        #pragma unroll
        for (int o = 16; o; o >>= 1) mm = fmaxf(mm, __shfl_xor_sync(~0u, mm, o));
        if (tid == 0) g_scal[3] = 1.0f / mm;
    }
}

__global__ void rowstats_k(const float* __restrict__ a, const float* __restrict__ hd,
                           const float* __restrict__ l1h,
                           float* __restrict__ out_hes, float* __restrict__ out_l1)
{
    __shared__ float s1s[4], s2s[4];
    int m = blockIdx.x, tid = threadIdx.x;
    float av = a[(size_t)m*BA + tid];
    float s1 = fabsf(av), s2 = av*av;
    #pragma unroll
    for (int o = 16; o; o >>= 1) {
        s1 += __shfl_xor_sync(~0u, s1, o);
        s2 += __shfl_xor_sync(~0u, s2, o);
    }
    if ((tid&31)==0) { s1s[tid>>5]=s1; s2s[tid>>5]=s2; }
    __syncthreads();
    if (tid == 0) {
        float t1 = s1s[0]+s1s[1]+s1s[2]+s1s[3];
        float t2 = s2s[0]+s2s[1]+s2s[2]+s2s[3];
        float he = hd[m]*RMC + t2*(1.0f/(BA*100.0f));
        out_l1[m] = l1h[m]*RMC + t1*(1.0f/(BA*100.0f));
        out_hes[m] = he;
        g_hes[m] = he;
        g_nsq[m] = 0.0f;
    }
}

__global__ void colnorm1_k(const float* __restrict__ NB) {
    int col = blockIdx.x*256 + threadIdx.x;
    int r0 = blockIdx.y*128;
    float s = 0.0f;
    for (int r = r0; r < r0+128; r++) {
        float v = NB[(size_t)r*BD + col];
        s = fmaf(v, v, s);
    }
    atomicAdd(&g_nsq[col], s);
}

__global__ void colnorm2_k(const float* __restrict__ NB, float* __restrict__ out) {
    int i = blockIdx.x*blockDim.x + threadIdx.x;
    if (i < ED*BD) out[i] = NB[i] * rsqrtf(g_nsq[i & (BD-1)]);
}

__global__ void copy_a_k(const float* __restrict__ a, float* __restrict__ out) {
    int i = blockIdx.x*blockDim.x + threadIdx.x;
    if (i < BD*BA) out[i] = a[i];
}

__global__ void sumI2_k(const float* __restrict__ I) {
    __shared__ float red[8];
    int tid = threadIdx.x;
    float s = 0.0f;
    for (int i = blockIdx.x*blockDim.x + tid; i < ED*BA; i += gridDim.x*blockDim.x) {
        float v = I[i];
        s = fmaf(v, v, s);
    }
    #pragma unroll
    for (int o = 16; o; o >>= 1) s += __shfl_xor_sync(~0u, s, o);
    if ((tid&31)==0) red[tid>>5] = s;
    __syncthreads();
    if (tid == 0) {
        float t = 0.0f;
        #pragma unroll
        for (int i = 0; i < 8; i++) t += red[i];
        atomicAdd(&g_scal[4], t);
    }
}

__global__ void scalarfin_k(const float* __restrict__ se, const float* __restrict__ ne,
                            float* __restrict__ out_snr)
{
    float ns = se[0]*RMC + g_scal[4]*0.01f;
    out_snr[0] = ns / (ne[0]*RMC);
}

extern "C" void kernel_launch(void* const* d_in, const int* in_sizes, int n_in,
                              void* d_out, int out_size)
{
    const float* I     = (const float*)d_in[0];
    const float* basis = (const float*)d_in[1];
    const float* hd    = (const float*)d_in[2];
    const float* l1h   = (const float*)d_in[3];
    const float* se    = (const float*)d_in[4];
    const float* ne    = (const float*)d_in[5];
    float* out = (float*)d_out;

    float *BT,*It,*a,*r,*S,*T0,*T1,*NB;
    cudaGetSymbolAddress((void**)&BT, g_BT);
    cudaGetSymbolAddress((void**)&It, g_It);
    cudaGetSymbolAddress((void**)&a,  g_a);
    cudaGetSymbolAddress((void**)&r,  g_r);
    cudaGetSymbolAddress((void**)&S,  g_S);
    cudaGetSymbolAddress((void**)&T0, g_T0);
    cudaGetSymbolAddress((void**)&T1, g_T1);
    cudaGetSymbolAddress((void**)&NB, g_NB);

    transpose_k<<<dim3(BD/32, ED/32), dim3(32,8)>>>(basis, BT, nullptr, ED, BD);
    transpose_k<<<dim3(ED/32, BA/32), dim3(32,8)>>>(I, It, r, BA, ED);
    init_k<<<(BD*BA+255)/256, 256>>>(a);

    // S = B B^T, then 6 squarings (renormalized) -> g_T0 holds dir(S^64)
    gemm_nt_k<0><<<dim3(ED/64, ED/16), 128>>>(basis, basis, S, nullptr, ED, BD);
    copyN_k<<<(ED*ED+255)/256, 256>>>(S, T0, ED*ED);
    float* sq[2] = {T0, T1};
    for (int i = 0; i < 6; i++) {
        diagmax_k<<<1, 1024>>>(sq[0]);
        gemm_nt_k<3><<<dim3(ED/64, ED/16), 128>>>(sq[0], sq[0], sq[1], nullptr, ED, ED);
        float* t = sq[0]; sq[0] = sq[1]; sq[1] = t;
    }
    // sq[0] == T0 after 6 swaps

    // persistent: power iteration + 500 ISTA iterations
    persist_k<<<GRID, 128>>>(basis);

    // epilogue
    rowstats_k<<<BD, 128>>>(a, hd, l1h, out + O_HES, out + O_L1);
    gemm_nt_k<4><<<dim3(BD/64, ED/16), 128>>>(r, a, NB, basis, BD, BA);
    colnorm1_k<<<dim3(BD/256, ED/128), 256>>>(NB);
    colnorm2_k<<<(ED*BD+255)/256, 256>>>(NB, out + O_BASIS);
    copy_a_k<<<(BD*BA+255)/256, 256>>>(a, out + O_A);
    sumI2_k<<<256, 256>>>(I);
    scalarfin_k<<<1, 1>>>(se, ne, out + O_SNR);
}